// round 17
// baseline (speedup 1.0000x reference)
#include <cuda_runtime.h>
#include <cstdint>

// Problem constants
#define BATCH 32
#define SEQ   128
#define DIM   256
#define MROWS (BATCH*SEQ)     // 4096
#define NSPLIT 16
#define JT    (SEQ/NSPLIT)    // 8
#define IT    16

typedef unsigned long long ull;

// ---------------- scratch (device globals; no allocation allowed) -----------
__device__ float g_XL[MROWS * DIM];
__device__ float g_XR[MROWS * DIM];
__device__ float g_part[NSPLIT * BATCH * DIM];   // abs-sum + folded linear term

// ---------------- packed f32x2 helpers ---------------------------------------
__device__ __forceinline__ ull fpk_dup(float x) {
    unsigned u = __float_as_uint(x);
    ull r;
    asm("mov.b64 %0, {%1, %1};" : "=l"(r) : "r"(u));
    return r;
}
__device__ __forceinline__ ull fpk2(float x, float y) {
    ull r;
    asm("mov.b64 %0, {%1, %2};" : "=l"(r)
        : "r"(__float_as_uint(x)), "r"(__float_as_uint(y)));
    return r;
}
__device__ __forceinline__ ull add2(ull a, ull b) {
    ull d;
    asm("add.rn.f32x2 %0, %1, %2;" : "=l"(d) : "l"(a), "l"(b));
    return d;
}
__device__ __forceinline__ ull fma2(ull a, ull b, ull c) {
    ull d;
    asm("fma.rn.f32x2 %0, %1, %2, %3;" : "=l"(d) : "l"(a), "l"(b), "l"(c));
    return d;
}
__device__ __forceinline__ float2 unpk(ull v) {
    unsigned lo, hi;
    asm("mov.b64 {%0, %1}, %2;" : "=r"(lo), "=r"(hi) : "l"(v));
    return make_float2(__uint_as_float(lo), __uint_as_float(hi));
}

// ---------------- bf16x2 helpers ---------------------------------------------
// pack two f32 -> bf16x2 (hi -> high half, lo -> low half)
__device__ __forceinline__ uint32_t bfpack(float hi, float lo) {
    uint32_t r;
    asm("cvt.rn.bf16x2.f32 %0, %1, %2;" : "=r"(r) : "f"(hi), "f"(lo));
    return r;
}
__device__ __forceinline__ uint32_t hadd2(uint32_t a, uint32_t b) {
    uint32_t d;
    asm("add.rn.bf16x2 %0, %1, %2;" : "=r"(d) : "r"(a), "r"(b));
    return d;
}

// ---------------- cp.async helpers ------------------------------------------
__device__ __forceinline__ void cpa16(uint32_t saddr, const void* gaddr) {
    asm volatile("cp.async.cg.shared.global [%0], [%1], 16;"
                 :: "r"(saddr), "l"(gaddr));
}
#define CP_COMMIT() asm volatile("cp.async.commit_group;")
#define CP_WAIT0()  asm volatile("cp.async.wait_group 0;")

// ---------------- tf32 mma helpers ------------------------------------------
__device__ __forceinline__ uint32_t to_tf32(uint32_t x) {
    uint32_t r;
    asm("cvt.rna.tf32.f32 %0, %1;" : "=r"(r) : "r"(x));
    return r;
}
__device__ __forceinline__ void ldm_x4(uint32_t& r0, uint32_t& r1,
                                       uint32_t& r2, uint32_t& r3, uint32_t addr) {
    asm volatile("ldmatrix.sync.aligned.m8n8.x4.shared.b16 {%0,%1,%2,%3}, [%4];"
                 : "=r"(r0), "=r"(r1), "=r"(r2), "=r"(r3) : "r"(addr));
}
__device__ __forceinline__ void mma_tf32(float* c, const uint32_t* a,
                                         uint32_t b0, uint32_t b1) {
    asm volatile("mma.sync.aligned.m16n8k8.row.col.f32.tf32.tf32.f32 "
                 "{%0,%1,%2,%3}, {%4,%5,%6,%7}, {%8,%9}, {%0,%1,%2,%3};"
                 : "+f"(c[0]), "+f"(c[1]), "+f"(c[2]), "+f"(c[3])
                 : "r"(a[0]), "r"(a[1]), "r"(a[2]), "r"(a[3]), "r"(b0), "r"(b1));
}

// ---------------------------------------------------------------------------
// Kernel 1: fused embedding gather + dual GEMM — tf32 tensor cores
//   64x128 tile, 256 threads (8 warps, warp tile 16m x 64n),
//   grid = (64, 4) = 256 blocks -> 2 blocks/SM (16 warps/SM, no idle SMs).
//   cp.async double-buffered static smem (2 x BK=16 stages, 30 KB).
// ---------------------------------------------------------------------------
#define BM 64
#define BN 128
#define BKK 16                        // k per stage (2 k8 steps)
#define NSTAGES (DIM / BKK)           // 16
#define PITCH 20                      // floats/row: 80B rows
#define A_FLOATS (BM * PITCH)         // 1280
#define B_FLOATS (BN * PITCH)         // 2560
#define STAGE_FLOATS (A_FLOATS + B_FLOATS)   // 3840 floats = 15 KB

__global__ void __launch_bounds__(256)
k_gemm(const int* __restrict__ X, const float* __restrict__ emb,
       const float* __restrict__ Wl, const float* __restrict__ bl,
       const float* __restrict__ Wr, const float* __restrict__ br)
{
    __shared__ float sm[2 * STAGE_FLOATS];   // 30 KB static
    __shared__ int   toks[BM];

    const int tid = threadIdx.x;
    const int bx = blockIdx.x, by = blockIdx.y;
    const bool isr = (by >= 2);
    const float* W    = isr ? Wr : Wl;
    const float* bias = isr ? br : bl;
    float*       Cout = isr ? g_XR : g_XL;
    const int nloc0 = (by & 1) * BN;

    if (tid < BM) toks[tid] = X[bx * BM + tid];
    __syncthreads();

    const uint32_t sb = (uint32_t)__cvta_generic_to_shared(sm);

    // loader mapping: 1 A-chunk (16B) + 2 B-chunks per thread per stage
    const int arow = tid >> 2;          // 0..63
    const int acol = (tid & 3) * 4;     // 0,4,8,12
    const int brow = tid >> 1;          // 0..127
    const int bcol = (tid & 1) * 8;     // 0 or 8

    const float* arow_g = emb + (size_t)toks[arow] * DIM + acol;
    const float* brow_g = W   + (size_t)(nloc0 + brow) * DIM + bcol;
    const uint32_t a_s  = sb + (uint32_t)(arow * PITCH + acol) * 4u;
    const uint32_t b_s  = sb + (uint32_t)(A_FLOATS + brow * PITCH + bcol) * 4u;

    auto load_stage = [&](int buf, int k0) {
        const uint32_t off = (uint32_t)(buf * STAGE_FLOATS) * 4u;
        cpa16(a_s + off,       arow_g + k0);
        cpa16(b_s + off,       brow_g + k0);
        cpa16(b_s + off + 16u, brow_g + k0 + 4);
    };

    // compute mapping: 8 warps = 4(m) x 2(n); warp tile 16m x 64n
    const int warp = tid >> 5;
    const int lane = tid & 31;
    const int M0w  = (warp >> 1) * 16;
    const int N0w  = (warp & 1) * 64;

    // ldmatrix lane-role offsets
    const int aRowOff = (lane & 7) + ((lane >> 3) & 1) * 8;  // row within m16
    const int aColOff = (lane >> 4) * 4;                     // k-half
    const int bRowOff = (lane >> 4) * 8 + (lane & 7);        // row within n16
    const int bColOff = ((lane >> 3) & 1) * 4;               // k-half

    float c[8][4];
    #pragma unroll
    for (int na = 0; na < 8; na++)
        #pragma unroll
        for (int q = 0; q < 4; q++) c[na][q] = 0.f;

    load_stage(0, 0);
    CP_COMMIT();

    for (int t = 0; t < NSTAGES; t++) {
        CP_WAIT0();
        __syncthreads();

        if (t + 1 < NSTAGES) {
            load_stage((t + 1) & 1, (t + 1) * BKK);
            CP_COMMIT();
        }

        const uint32_t stage  = sb + (uint32_t)((t & 1) * STAGE_FLOATS) * 4u;
        const uint32_t bstage = stage + A_FLOATS * 4u;

        #pragma unroll
        for (int k8 = 0; k8 < 2; k8++) {
            const int K0 = k8 * 8;

            // A fragment: one ldmatrix.x4 for the single m16 atom
            uint32_t a[4];
            {
                uint32_t addr = stage +
                    (uint32_t)((M0w + aRowOff) * PITCH + K0 + aColOff) * 4u;
                ldm_x4(a[0], a[1], a[2], a[3], addr);
                #pragma unroll
                for (int q = 0; q < 4; q++) a[q] = to_tf32(a[q]);
            }

            // B fragments: one ldmatrix.x4 per n16 pair
            #pragma unroll
            for (int np = 0; np < 4; np++) {
                uint32_t b0, b1, b2, b3;
                uint32_t addr = bstage +
                    (uint32_t)((N0w + np * 16 + bRowOff) * PITCH + K0 + bColOff) * 4u;
                ldm_x4(b0, b1, b2, b3, addr);
                b0 = to_tf32(b0); b1 = to_tf32(b1);
                b2 = to_tf32(b2); b3 = to_tf32(b3);

                mma_tf32(c[np * 2 + 0], a, b0, b1);
                mma_tf32(c[np * 2 + 1], a, b2, b3);
            }
        }
    }

    // epilogue: bias + store. lane g=lane>>2 -> rows g, g+8; cq=lane&3 -> cols 2cq,2cq+1
    {
        const int g  = lane >> 2;
        const int cq = lane & 3;
        #pragma unroll
        for (int na = 0; na < 8; na++) {
            const int gc = nloc0 + N0w + na * 8 + 2 * cq;
            const float b0v = bias[gc], b1v = bias[gc + 1];
            const int r0 = bx * BM + M0w + g;
            float2 lo = make_float2(c[na][0] + b0v, c[na][1] + b1v);
            float2 hi = make_float2(c[na][2] + b0v, c[na][3] + b1v);
            *(float2*)(Cout + (size_t)r0 * DIM + gc)       = lo;
            *(float2*)(Cout + (size_t)(r0 + 8) * DIM + gc) = hi;
        }
    }
}

// ---------------------------------------------------------------------------
// Kernel 2: pairwise abs-sum partials, bf16x2 HADD2 pipe (rt2 = 2x fp32 tput).
//   part[js,b,d] = sum_{i,j in js} |xl_i+xr_j| + 8*sum_i xl_i + 128*sum_{j in js} xr_j
//   Adds + abs + depth-3 tree in bf16x2; per-ii tree sum folded into fp32
//   accumulators (no long bf16 chains). Linear terms stay fp32.
// ---------------------------------------------------------------------------
__global__ void __launch_bounds__(128) k_pair()
{
    const int b  = blockIdx.x;
    const int js = blockIdx.y;
    const int tid = threadIdx.x;

    __shared__ float xls[IT][DIM];

    uint32_t xrh[JT];
    ull xrsum;
    {
        const float* base = g_XR + (size_t)(b * SEQ + js * JT) * DIM + tid * 2;
        ull xr[JT];
        #pragma unroll
        for (int j = 0; j < JT; j++)
            xr[j] = *(const ull*)(base + (size_t)j * DIM);
        xrsum = xr[0];
        #pragma unroll
        for (int j = 1; j < JT; j++) xrsum = add2(xrsum, xr[j]);
        #pragma unroll
        for (int j = 0; j < JT; j++) {
            float2 f = unpk(xr[j]);
            xrh[j] = bfpack(f.y, f.x);
        }
    }

    float accx = 0.f, accy = 0.f;
    ull xlacc = 0;

    for (int i0 = 0; i0 < SEQ; i0 += IT) {
        #pragma unroll
        for (int rr = 0; rr < IT; rr++) {
            *(ull*)&xls[rr][tid * 2] =
                *(const ull*)(g_XL + (size_t)(b * SEQ + i0 + rr) * DIM + tid * 2);
        }
        __syncthreads();

        #pragma unroll
        for (int ii = 0; ii < IT; ii++) {
            ull xl = *(const ull*)&xls[ii][tid * 2];
            xlacc = add2(xlacc, xl);
            float2 xf = unpk(xl);
            uint32_t xlh = bfpack(xf.y, xf.x);

            uint32_t h[JT];
            #pragma unroll
            for (int j = 0; j < JT; j++)
                h[j] = hadd2(xlh, xrh[j]) & 0x7FFF7FFFu;   // add + abs (alu)

            // depth-3 bf16 tree over the 8 j's
            uint32_t s01 = hadd2(h[0], h[1]);
            uint32_t s23 = hadd2(h[2], h[3]);
            uint32_t s45 = hadd2(h[4], h[5]);
            uint32_t s67 = hadd2(h[6], h[7]);
            uint32_t s03 = hadd2(s01, s23);
            uint32_t s47 = hadd2(s45, s67);
            uint32_t s   = hadd2(s03, s47);

            // expand bf16x2 -> two f32 (shift/mask on alu) and fold into fp32
            accx += __uint_as_float(s << 16);
            accy += __uint_as_float(s & 0xFFFF0000u);
        }
        __syncthreads();
    }

    ull acc0 = fpk2(accx, accy);
    acc0 = fma2(fpk_dup(8.0f),   xlacc, acc0);
    acc0 = fma2(fpk_dup(128.0f), xrsum, acc0);

    float2 res = unpk(acc0);
    float* outp = g_part + (size_t)(js * BATCH + b) * DIM + tid * 2;
    outp[0] = res.x;
    outp[1] = res.y;
}

// ---------------------------------------------------------------------------
// Kernel 3: reduce partials -> pooled; out = pooled @ W_rn^T + n^2 * b_rn
// ---------------------------------------------------------------------------
__global__ void __launch_bounds__(256)
k_final(const float* __restrict__ Wrn, const float* __restrict__ brn,
        float* __restrict__ out)
{
    const int b   = blockIdx.x;
    const int nc  = blockIdx.y;
    const int tid = threadIdx.x;
    __shared__ float pooled[DIM];

    {
        float p = 0.f;
        #pragma unroll
        for (int s = 0; s < NSPLIT; s++)
            p += g_part[(size_t)(s * BATCH + b) * DIM + tid];
        pooled[tid] = 0.5f * p;
    }
    __syncthreads();

    const int n  = nc * 32 + (tid >> 3);
    const int d0 = (tid & 7) * 32;
    const float4* w  = (const float4*)(Wrn + (size_t)n * DIM + d0);
    const float4* pp = (const float4*)(pooled + d0);
    float acc = 0.f;
    #pragma unroll
    for (int i = 0; i < 8; i++) {
        float4 wv = w[i];
        float4 pv = pp[i];
        acc += wv.x * pv.x + wv.y * pv.y + wv.z * pv.z + wv.w * pv.w;
    }
    acc += __shfl_down_sync(0xffffffffu, acc, 4, 8);
    acc += __shfl_down_sync(0xffffffffu, acc, 2, 8);
    acc += __shfl_down_sync(0xffffffffu, acc, 1, 8);
    if ((tid & 7) == 0)
        out[b * DIM + n] = acc + 16384.0f * brn[n];
}

// ---------------------------------------------------------------------------
extern "C" void kernel_launch(void* const* d_in, const int* in_sizes, int n_in,
                              void* d_out, int out_size)
{
    const int*   X    = (const int*)  d_in[0];
    const float* emb  = (const float*)d_in[1];
    const float* Wl   = (const float*)d_in[2];
    const float* bl   = (const float*)d_in[3];
    const float* Wr   = (const float*)d_in[4];
    const float* br   = (const float*)d_in[5];
    const float* Wrn  = (const float*)d_in[6];
    const float* brn  = (const float*)d_in[7];
    float*       out  = (float*)d_out;

    k_gemm <<<dim3(MROWS / BM, 4), 256>>>(X, emb, Wl, bl, Wr, br);
    k_pair <<<dim3(BATCH, NSPLIT), 128>>>();
    k_final<<<dim3(BATCH, 8), 256>>>(Wrn, brn, out);
}